// round 3
// baseline (speedup 1.0000x reference)
#include <cuda_runtime.h>

// PureCartesianTensorProductO3Sparse — f32x2 o-pair version.
// Weights in smem as (o, o+8) interleaved pairs; x rows staged TRANSPOSED so
// stage-2 operands are contiguous over the channel index. fma.rn.f32x2
// computes both output channels per instruction.

#define PACK2(d,x,y) asm("mov.b64 %0, {%1, %2};" : "=l"(d) : "f"(x), "f"(y))
#define UNPK2(x,y,d) asm("mov.b64 {%0, %1}, %2;" : "=f"(x), "=f"(y) : "l"(d))
#define FMA2(d,a,b,c) asm("fma.rn.f32x2 %0, %1, %2, %3;" : "=l"(d) : "l"(a), "l"(b), "l"(c))
#define ADD2(d,a,b)   asm("add.rn.f32x2 %0, %1, %2;" : "=l"(d) : "l"(a), "l"(b))

typedef unsigned long long u64;

constexpr int ROW_IN  = 416;
constexpr int ROW_PAD = 212;           // staged row stride (slot bank spread = 20)
constexpr int RPT     = 64;            // rows per tile
constexpr int THREADS = 512;           // 16 warps
constexpr int OL_STR  = 36;            // floats per (p,a,olane): 32 data + 4 pad
constexpr int A_STR   = 8 * OL_STR;    // 288
constexpr int P_STR   = 16 * A_STR;    // 4608
constexpr int WSMF    = 6 * P_STR;     // 27648 floats = 108 KB
constexpr int WELEMS  = 6 * 16 * 16 * 16;

__global__ __launch_bounds__(THREADS, 1)
void tp_o3_kernel(const float* __restrict__ x1,
                  const float* __restrict__ x2,
                  const float* __restrict__ wgt,
                  float* __restrict__ out,
                  int N)
{
    extern __shared__ float smem[];
    float* ws  = smem;                       // weight pairs
    float* x1s = smem + WSMF;                // 64 x 212 (transposed rows)
    float* x2s = x1s + RPT * ROW_PAD;

    const int tid = threadIdx.x;

    // ---- weights: gmem [p][o][a][b] -> smem pairs [p][a][olane]{b, o/o+8}
    for (int idx = tid; idx < WELEMS; idx += THREADS) {
        int p = idx >> 12;
        int o = (idx >> 8) & 15;
        int a = (idx >> 4) & 15;
        int b = idx & 15;
        int olane = o & 7, oh = o >> 3;
        ws[p * P_STR + a * A_STR + olane * OL_STR + 2 * b + oh] = wgt[idx];
    }
    __syncthreads();

    const int olane = tid & 7;
    const int slot  = tid >> 3;              // 0..63
    const int ntiles = (N + RPT - 1) / RPT;

    const float* w0base = ws + 0 * P_STR + olane * OL_STR;
    const float* w1base = ws + 1 * P_STR + olane * OL_STR;
    const float* w2base = ws + 2 * P_STR + olane * OL_STR;
    const float* w3base = ws + 3 * P_STR + olane * OL_STR;
    const float* w4base = ws + 4 * P_STR + olane * OL_STR;
    const float* w5base = ws + 5 * P_STR + olane * OL_STR;

    for (int tile = blockIdx.x; tile < ntiles; tile += (int)gridDim.x) {
        const int row0  = tile * RPT;
        const int nrows = min(RPT, N - row0);

        // ---- stage rows transposed: [0..16)=L0, [16..64)=L1t[i][16], [64..208)=L2t[k][16]
        {
            const int tot = nrows * 208;
            for (int idx = tid; idx < tot; idx += THREADS) {
                int r = idx / 208, c = idx - r * 208;
                int toff;
                if (c < 16) {
                    toff = c;
                } else if (c < 64) {
                    int q = c - 16;
                    toff = 16 + (q % 3) * 16 + q / 3;
                } else {
                    int q = c - 64;
                    toff = 64 + (q % 9) * 16 + q / 9;
                }
                size_t g = (size_t)(row0 + r) * ROW_IN + c;
                x1s[r * ROW_PAD + toff] = x1[g];
                x2s[r * ROW_PAD + toff] = x2[g];
            }
        }
        __syncthreads();

        if (slot < nrows) {
            const float* xa = x1s + slot * ROW_PAD;
            const float* xb = x2s + slot * ROW_PAD;

            u64 acc0p = 0ull;
            u64 acc1p[3] = {0ull, 0ull, 0ull};
            u64 acc2p[9] = {0ull,0ull,0ull,0ull,0ull,0ull,0ull,0ull,0ull};

            u64 t[16];

            // t[b] (pair over o) = sum_a A0[a] * Wpair[a][b]
            auto stage1 = [&](const float* wbase) {
                #pragma unroll
                for (int b = 0; b < 16; b++) t[b] = 0ull;
                #pragma unroll
                for (int a = 0; a < 16; a++) {
                    float av = xa[a];
                    u64 avd; PACK2(avd, av, av);
                    const ulonglong2* wv =
                        reinterpret_cast<const ulonglong2*>(wbase + a * A_STR);
                    #pragma unroll
                    for (int j = 0; j < 8; j++) {
                        ulonglong2 q = wv[j];
                        FMA2(t[2*j],   avd, q.x, t[2*j]);
                        FMA2(t[2*j+1], avd, q.y, t[2*j+1]);
                    }
                }
            };

            // ---- path 0: stage1 then dot with B0
            stage1(w0base);
            {
                u64 u0 = 0ull, u1 = 0ull;
                #pragma unroll
                for (int b = 0; b < 16; b += 2) {
                    float e0 = xb[b], e1 = xb[b + 1];
                    u64 d0, d1; PACK2(d0, e0, e0); PACK2(d1, e1, e1);
                    FMA2(u0, t[b],   d0, u0);
                    FMA2(u1, t[b+1], d1, u1);
                }
                ADD2(acc0p, u0, u1);
            }

            // ---- path 1: stage1 then outer with B1t[i][b]
            stage1(w1base);
            #pragma unroll
            for (int i = 0; i < 3; i++) {
                const float4* ev = reinterpret_cast<const float4*>(xb + 16 + i * 16);
                float e[16];
                #pragma unroll
                for (int j = 0; j < 4; j++) {
                    float4 q = ev[j];
                    e[4*j] = q.x; e[4*j+1] = q.y; e[4*j+2] = q.z; e[4*j+3] = q.w;
                }
                u64 u0 = acc1p[i], u1 = 0ull;
                #pragma unroll
                for (int b = 0; b < 16; b += 2) {
                    u64 d0, d1; PACK2(d0, e[b], e[b]); PACK2(d1, e[b+1], e[b+1]);
                    FMA2(u0, t[b],   d0, u0);
                    FMA2(u1, t[b+1], d1, u1);
                }
                ADD2(acc1p[i], u0, u1);
            }

            // ---- path 2: stage1 then outer with B2t[k][b]
            stage1(w2base);
            #pragma unroll
            for (int k = 0; k < 9; k++) {
                const float4* ev = reinterpret_cast<const float4*>(xb + 64 + k * 16);
                float e[16];
                #pragma unroll
                for (int j = 0; j < 4; j++) {
                    float4 q = ev[j];
                    e[4*j] = q.x; e[4*j+1] = q.y; e[4*j+2] = q.z; e[4*j+3] = q.w;
                }
                u64 u0 = acc2p[k], u1 = 0ull;
                #pragma unroll
                for (int b = 0; b < 16; b += 2) {
                    u64 d0, d1; PACK2(d0, e[b], e[b]); PACK2(d1, e[b+1], e[b+1]);
                    FMA2(u0, t[b],   d0, u0);
                    FMA2(u1, t[b+1], d1, u1);
                }
                ADD2(acc2p[k], u0, u1);
            }

            // ---- B0 duplicated pairs for paths 3 & 5
            u64 B0dup[16];
            #pragma unroll
            for (int b = 0; b < 16; b++) {
                float e = xb[b];
                PACK2(B0dup[b], e, e);
            }

            auto dotB0 = [&](const float* wa) -> u64 {
                u64 s0 = 0ull, s1 = 0ull;
                const ulonglong2* wv = reinterpret_cast<const ulonglong2*>(wa);
                #pragma unroll
                for (int j = 0; j < 8; j++) {
                    ulonglong2 q = wv[j];
                    FMA2(s0, q.x, B0dup[2*j],   s0);
                    FMA2(s1, q.y, B0dup[2*j+1], s1);
                }
                u64 s; ADD2(s, s0, s1);
                return s;
            };

            // ---- path 3: s_pair[a] = W3·B0 ; acc1 += s_pair * A1t[i][a]
            #pragma unroll
            for (int a = 0; a < 16; a++) {
                u64 s = dotB0(w3base + a * A_STR);
                #pragma unroll
                for (int i = 0; i < 3; i++) {
                    float e = xa[16 + i * 16 + a];
                    u64 ed; PACK2(ed, e, e);
                    FMA2(acc1p[i], s, ed, acc1p[i]);
                }
            }

            // ---- path 5: s2[a] = W5·B0 ; acc2 += s2[a] * A2t[k][a]
            {
                u64 s2[16];
                #pragma unroll
                for (int a = 0; a < 16; a++) s2[a] = dotB0(w5base + a * A_STR);
                #pragma unroll
                for (int k = 0; k < 9; k++) {
                    const float4* ev = reinterpret_cast<const float4*>(xa + 64 + k * 16);
                    float e[16];
                    #pragma unroll
                    for (int j = 0; j < 4; j++) {
                        float4 q = ev[j];
                        e[4*j] = q.x; e[4*j+1] = q.y; e[4*j+2] = q.z; e[4*j+3] = q.w;
                    }
                    u64 u0 = acc2p[k], u1 = 0ull;
                    #pragma unroll
                    for (int a = 0; a < 16; a += 2) {
                        u64 d0, d1; PACK2(d0, e[a], e[a]); PACK2(d1, e[a+1], e[a+1]);
                        FMA2(u0, s2[a],   d0, u0);
                        FMA2(u1, s2[a+1], d1, u1);
                    }
                    ADD2(acc2p[k], u0, u1);
                }
            }

            // ---- path 4: v{o}[j] = sum_b W4[o][a][b] B1t[j][b] ; acc2 += A1[a,i] v[j]
            {
                float B1tf[48];
                #pragma unroll
                for (int i = 0; i < 3; i++) {
                    const float4* ev = reinterpret_cast<const float4*>(xb + 16 + i * 16);
                    #pragma unroll
                    for (int j = 0; j < 4; j++) {
                        float4 q = ev[j];
                        B1tf[i*16 + 4*j]   = q.x; B1tf[i*16 + 4*j+1] = q.y;
                        B1tf[i*16 + 4*j+2] = q.z; B1tf[i*16 + 4*j+3] = q.w;
                    }
                }
                #pragma unroll
                for (int a = 0; a < 16; a++) {
                    const float4* wf =
                        reinterpret_cast<const float4*>(w4base + a * A_STR);
                    float va0=0.f,va1=0.f,va2=0.f, vb0=0.f,vb1=0.f,vb2=0.f;
                    float wa0=0.f,wa1=0.f,wa2=0.f, wb0=0.f,wb1=0.f,wb2=0.f;
                    #pragma unroll
                    for (int j = 0; j < 8; j++) {
                        float4 f = wf[j];          // (o1,b) (o2,b) (o1,b+1) (o2,b+1)
                        float e00 = B1tf[0*16 + 2*j],   e10 = B1tf[1*16 + 2*j],   e20 = B1tf[2*16 + 2*j];
                        float e01 = B1tf[0*16 + 2*j+1], e11 = B1tf[1*16 + 2*j+1], e21 = B1tf[2*16 + 2*j+1];
                        va0 = fmaf(f.x, e00, va0); va1 = fmaf(f.x, e10, va1); va2 = fmaf(f.x, e20, va2);
                        wa0 = fmaf(f.y, e00, wa0); wa1 = fmaf(f.y, e10, wa1); wa2 = fmaf(f.y, e20, wa2);
                        vb0 = fmaf(f.z, e01, vb0); vb1 = fmaf(f.z, e11, vb1); vb2 = fmaf(f.z, e21, vb2);
                        wb0 = fmaf(f.w, e01, wb0); wb1 = fmaf(f.w, e11, wb1); wb2 = fmaf(f.w, e21, wb2);
                    }
                    u64 vp0, vp1, vp2;
                    PACK2(vp0, va0 + vb0, wa0 + wb0);
                    PACK2(vp1, va1 + vb1, wa1 + wb1);
                    PACK2(vp2, va2 + vb2, wa2 + wb2);
                    float a10 = xa[16 + 0*16 + a];
                    float a11 = xa[16 + 1*16 + a];
                    float a12 = xa[16 + 2*16 + a];
                    u64 d0, d1, d2; PACK2(d0, a10, a10); PACK2(d1, a11, a11); PACK2(d2, a12, a12);
                    FMA2(acc2p[0], d0, vp0, acc2p[0]);
                    FMA2(acc2p[1], d0, vp1, acc2p[1]);
                    FMA2(acc2p[2], d0, vp2, acc2p[2]);
                    FMA2(acc2p[3], d1, vp0, acc2p[3]);
                    FMA2(acc2p[4], d1, vp1, acc2p[4]);
                    FMA2(acc2p[5], d1, vp2, acc2p[5]);
                    FMA2(acc2p[6], d2, vp0, acc2p[6]);
                    FMA2(acc2p[7], d2, vp1, acc2p[7]);
                    FMA2(acc2p[8], d2, vp2, acc2p[8]);
                }
            }

            // ---- unpack and store (first half of the row)
            const int o1 = olane, o2 = olane + 8;
            float* orow = out + (size_t)(row0 + slot) * ROW_IN;
            {
                float p1, p2;
                UNPK2(p1, p2, acc0p);
                orow[o1] = p1; orow[o2] = p2;
                #pragma unroll
                for (int i = 0; i < 3; i++) {
                    UNPK2(p1, p2, acc1p[i]);
                    orow[16 + 3*o1 + i] = p1;
                    orow[16 + 3*o2 + i] = p2;
                }
                #pragma unroll
                for (int k = 0; k < 9; k++) {
                    UNPK2(p1, p2, acc2p[k]);
                    orow[64 + 9*o1 + k] = p1;
                    orow[64 + 9*o2 + k] = p2;
                }
            }
        }

        // ---- zero the s=1 half (cols 208..415)
        {
            float4 z = make_float4(0.f, 0.f, 0.f, 0.f);
            float4* og = reinterpret_cast<float4*>(out) + (size_t)row0 * 104;
            for (int i = tid; i < nrows * 52; i += THREADS) {
                int r = i / 52, c = i - r * 52;
                og[(size_t)r * 104 + 52 + c] = z;
            }
        }
        __syncthreads();
    }
}

extern "C" void kernel_launch(void* const* d_in, const int* in_sizes, int n_in,
                              void* d_out, int out_size)
{
    const float* x1 = (const float*)d_in[0];
    const float* x2 = (const float*)d_in[1];
    const float* w  = (const float*)d_in[2];
    float* out = (float*)d_out;
    const int N = in_sizes[0] / ROW_IN;

    const int smem_bytes = (WSMF + 2 * RPT * ROW_PAD) * (int)sizeof(float); // 219136

    int smcount = 0;
    cudaDeviceGetAttribute(&smcount, cudaDevAttrMultiProcessorCount, 0);
    if (smcount <= 0) smcount = 148;
    cudaFuncSetAttribute(tp_o3_kernel, cudaFuncAttributeMaxDynamicSharedMemorySize,
                         smem_bytes);

    tp_o3_kernel<<<smcount, THREADS, smem_bytes>>>(x1, x2, w, out, N);
}